// round 10
// baseline (speedup 1.0000x reference)
#include <cuda_runtime.h>
#include <cuda_bf16.h>
#include <math.h>
#include <stdint.h>

#define DIM 256
#define NTOT 100000
#define ETRI 400000
#define NVALMAX 100000
#define NATTMAX 1001
#define KPAD_VAL 320
#define MT_S 40   // smem row stride in bf16 (80B): conflict-free for ldmatrix 8-row phases

// dynamic smem per buffer: A 128xMT_S hi+lo, B 128xMT_S hi+lo
#define OFF_AH 0
#define OFF_AL 10240
#define OFF_BH 20480
#define OFF_BL 30720
#define BUFSZ  40960
#define SMEM_TOT (2 * BUFSZ)

// ---------------- scratch ----------------
__device__ float g_valW[NVALMAX * DIM];
__device__ float g_attW[NATTMAX * DIM];
__device__ float g_attdot[NATTMAX];
__device__ float g_entdot[NTOT];
__device__ int   g_cnt[NTOT];
__device__ int   g_ptr[NTOT + 1];
__device__ int   g_eptr[NTOT + 1];
__device__ int   g_fill[NTOT];
__device__ int   g_idx[ETRI];
__device__ int   g_bsum[128];
__device__ int   g_boff[128];
__device__ float g_F1[NTOT * DIM];
__device__ float g_F2[NTOT * DIM];
// bf16 hi/lo A operands (sized for valW use: NVALMAX x KPAD_VAL >= NTOT x DIM)
__device__ __nv_bfloat16 g_xa_h[NVALMAX * KPAD_VAL];
__device__ __nv_bfloat16 g_xa_l[NVALMAX * KPAD_VAL];
__device__ __nv_bfloat16 g_wet_h[DIM * KPAD_VAL];
__device__ __nv_bfloat16 g_wet_l[DIM * KPAD_VAL];
__device__ __nv_bfloat16 g_w1t_h[DIM * DIM];
__device__ __nv_bfloat16 g_w1t_l[DIM * DIM];
__device__ __nv_bfloat16 g_w2t_h[DIM * DIM];
__device__ __nv_bfloat16 g_w2t_l[DIM * DIM];

// ---------------- PTX wrappers ----------------
__device__ __forceinline__ void mma16816(float* c, const uint32_t* a, const uint32_t* b) {
    asm volatile(
        "mma.sync.aligned.m16n8k16.row.col.f32.bf16.bf16.f32 "
        "{%0,%1,%2,%3}, {%4,%5,%6,%7}, {%8,%9}, {%0,%1,%2,%3};"
        : "+f"(c[0]), "+f"(c[1]), "+f"(c[2]), "+f"(c[3])
        : "r"(a[0]), "r"(a[1]), "r"(a[2]), "r"(a[3]), "r"(b[0]), "r"(b[1]));
}
#define LDMX4(r0, r1, r2, r3, addr) \
    asm volatile("ldmatrix.sync.aligned.m8n8.x4.shared.b16 {%0,%1,%2,%3}, [%4];" \
        : "=r"(r0), "=r"(r1), "=r"(r2), "=r"(r3) : "r"(addr))
#define CP_ASYNC16(saddr, gptr) \
    asm volatile("cp.async.ca.shared.global [%0], [%1], 16;" :: "r"(saddr), "l"(gptr))
#define CP_COMMIT() asm volatile("cp.async.commit_group;" ::: "memory")
#define CP_WAIT1() asm volatile("cp.async.wait_group 1;" ::: "memory")
#define CP_WAIT0() asm volatile("cp.async.wait_group 0;" ::: "memory")

// ---------------- HMMA split GEMM: 128x128 CTA tile, 4 warps of 64x64 ----------------
// A pre-split bf16 hi/lo [M, Kpad]; B hi/lo [256, Kpad]. D = AhBh + AlBh + AhBl.
// MODE 0: C = AB ; MODE 1: C = res + relu(AB+bias) ; MODE 2: C = res + AB + bias
template <int MODE>
__global__ void __launch_bounds__(128, 2)
mma_gemm_k(const __nv_bfloat16* __restrict__ Ah, const __nv_bfloat16* __restrict__ Al,
           int Kpad,
           const __nv_bfloat16* __restrict__ Bh, const __nv_bfloat16* __restrict__ Bl,
           int M,
           const float* __restrict__ bias, const float* __restrict__ res,
           float* __restrict__ C) {
    extern __shared__ char smem_dyn[];
    uint32_t smem_b = (uint32_t)__cvta_generic_to_shared(smem_dyn);
    int tid = threadIdx.x;
    int wid = tid >> 5, lane = tid & 31;
    int wm = wid & 1;      // 2 warp-rows of 64
    int wn = wid >> 1;     // 2 warp-cols of 64
    int row0 = blockIdx.y * 128;
    int col0 = blockIdx.x * 128;

    float acc[4][8][4];
    #pragma unroll
    for (int mt = 0; mt < 4; mt++)
        #pragma unroll
        for (int nt = 0; nt < 8; nt++)
            #pragma unroll
            for (int q = 0; q < 4; q++) acc[mt][nt][q] = 0.f;

    // copy mapping: thread t handles A row t and B row t (128 rows each)
    int gr = row0 + tid;
    bool arow_ok = gr < M;
    const __nv_bfloat16* AhRow = Ah + (size_t)(arow_ok ? gr : 0) * Kpad;
    const __nv_bfloat16* AlRow = Al + (size_t)(arow_ok ? gr : 0) * Kpad;
    const __nv_bfloat16* BhRow = Bh + (size_t)(col0 + tid) * Kpad;
    const __nv_bfloat16* BlRow = Bl + (size_t)(col0 + tid) * Kpad;
    uint32_t srow = (uint32_t)(tid * MT_S * 2);

    auto copyChunk = [&](int buf, int k0) {
        uint32_t b = smem_b + buf * BUFSZ + srow;
        #pragma unroll
        for (int j = 0; j < 4; j++) {
            uint32_t so = (uint32_t)(j * 16);
            CP_ASYNC16(b + OFF_AH + so, AhRow + k0 + j * 8);
            CP_ASYNC16(b + OFF_AL + so, AlRow + k0 + j * 8);
            CP_ASYNC16(b + OFF_BH + so, BhRow + k0 + j * 8);
            CP_ASYNC16(b + OFF_BL + so, BlRow + k0 + j * 8);
        }
        CP_COMMIT();
    };

    // ldmatrix lane-address components
    int a_row = wm * 64 + (lane & 15);                         // + mt*16
    int a_colsel = (lane >> 4) * 8;
    int b_row = wn * 64 + ((lane >> 4) ? 8 : 0) + (lane & 7);  // + p*16
    int b_colsel = ((lane >> 3) & 1) * 8;

    int nch = Kpad / 32;
    copyChunk(0, 0);
    if (nch > 1) copyChunk(1, 32);

    for (int ci = 0; ci < nch; ci++) {
        if (ci + 1 < nch) { CP_WAIT1(); } else { CP_WAIT0(); }
        __syncthreads();
        uint32_t bufb = smem_b + (ci & 1) * BUFSZ;
        #pragma unroll
        for (int ks = 0; ks < 2; ks++) {
            uint32_t aH[4][4], aL[4][4];
            #pragma unroll
            for (int mt = 0; mt < 4; mt++) {
                uint32_t off = (uint32_t)(((a_row + mt * 16) * MT_S + ks * 16 + a_colsel) * 2);
                LDMX4(aH[mt][0], aH[mt][1], aH[mt][2], aH[mt][3], bufb + OFF_AH + off);
                LDMX4(aL[mt][0], aL[mt][1], aL[mt][2], aL[mt][3], bufb + OFF_AL + off);
            }
            #pragma unroll
            for (int p = 0; p < 4; p++) {
                uint32_t off = (uint32_t)(((b_row + p * 16) * MT_S + ks * 16 + b_colsel) * 2);
                uint32_t h0, h1, h2, h3, l0, l1, l2, l3;
                LDMX4(h0, h1, h2, h3, bufb + OFF_BH + off);
                LDMX4(l0, l1, l2, l3, bufb + OFF_BL + off);
                uint32_t bH0[2] = {h0, h1}, bH1[2] = {h2, h3};
                uint32_t bL0[2] = {l0, l1}, bL1[2] = {l2, l3};
                #pragma unroll
                for (int mt = 0; mt < 4; mt++) {
                    mma16816(acc[mt][2 * p],     aH[mt], bH0);
                    mma16816(acc[mt][2 * p],     aL[mt], bH0);
                    mma16816(acc[mt][2 * p],     aH[mt], bL0);
                    mma16816(acc[mt][2 * p + 1], aH[mt], bH1);
                    mma16816(acc[mt][2 * p + 1], aL[mt], bH1);
                    mma16816(acc[mt][2 * p + 1], aH[mt], bL1);
                }
            }
        }
        __syncthreads();   // all warps done reading buf(ci) before it is refilled
        if (ci + 2 < nch) copyChunk(ci & 1, (ci + 2) * 32);
    }

    #pragma unroll
    for (int mt = 0; mt < 4; mt++) {
        #pragma unroll
        for (int half = 0; half < 2; half++) {
            int r = row0 + wm * 64 + mt * 16 + (lane >> 2) + half * 8;
            if (r >= M) continue;
            #pragma unroll
            for (int nt = 0; nt < 8; nt++) {
                int c = col0 + wn * 64 + nt * 8 + (lane & 3) * 2;
                float2 v;
                v.x = acc[mt][nt][half * 2 + 0];
                v.y = acc[mt][nt][half * 2 + 1];
                if (MODE >= 1) {
                    const float2 bb = *(const float2*)&bias[c];
                    v.x += bb.x; v.y += bb.y;
                    if (MODE == 1) { v.x = fmaxf(v.x, 0.f); v.y = fmaxf(v.y, 0.f); }
                    const float2 rr = *(const float2*)&res[(size_t)r * 256 + c];
                    v.x += rr.x; v.y += rr.y;
                }
                *(float2*)&C[(size_t)r * 256 + c] = v;
            }
        }
    }
}

// ---------------- fp32 -> bf16 hi/lo split (row pad to Kpad) ----------------
__global__ void split_pad_k(const float* __restrict__ src, int M, int K, int Kpad,
                            __nv_bfloat16* __restrict__ hi, __nv_bfloat16* __restrict__ lo) {
    long long idx = (long long)blockIdx.x * blockDim.x + threadIdx.x;
    long long tot = (long long)M * Kpad;
    if (idx >= tot) return;
    int k = (int)(idx % Kpad);
    long long r = idx / Kpad;
    float v = (k < K) ? src[r * K + k] : 0.f;
    __nv_bfloat16 h = __float2bfloat16(v);
    hi[idx] = h;
    lo[idx] = __float2bfloat16(v - __bfloat162float(h));
}
// weight transpose + hi/lo split
__global__ void tsplit_k(const float* __restrict__ src, int K, int Kpad,
                         __nv_bfloat16* __restrict__ hi, __nv_bfloat16* __restrict__ lo) {
    int idx = blockIdx.x * blockDim.x + threadIdx.x;
    if (idx >= 256 * Kpad) return;
    int k = idx % Kpad;
    int n = idx / Kpad;
    float v = (k < K) ? src[(size_t)k * 256 + n] : 0.f;
    __nv_bfloat16 h = __float2bfloat16(v);
    hi[idx] = h;
    lo[idx] = __float2bfloat16(v - __bfloat162float(h));
}

// ---------------- stacked SIMT pipeline kernels ----------------
__global__ void zero_int_k(int* p, int n) {
    int i = blockIdx.x * blockDim.x + threadIdx.x;
    if (i < n) p[i] = 0;
}
__global__ void att_k(const float* __restrict__ att_feats,
                      const float* __restrict__ W_enc,
                      const float* __restrict__ a_w, int natt) {
    int r = blockIdx.x;
    int d = threadIdx.x;
    __shared__ float sh[DIM];
    __shared__ float sred[8];
    sh[d] = att_feats[(size_t)r * DIM + d];
    __syncthreads();
    float acc = 0.f;
    #pragma unroll 8
    for (int k = 0; k < DIM; k++) acc += sh[k] * W_enc[(size_t)k * DIM + d];
    g_attW[(size_t)r * DIM + d] = acc;
    float v = sh[d] * a_w[DIM + d];
    for (int o = 16; o; o >>= 1) v += __shfl_xor_sync(0xffffffffu, v, o);
    if ((d & 31) == 0) sred[d >> 5] = v;
    __syncthreads();
    if (d == 0) {
        float s = 0.f;
        #pragma unroll
        for (int i = 0; i < 8; i++) s += sred[i];
        g_attdot[r] = s;
    }
}
__global__ void entdot_all_k(const float* __restrict__ ent0, const float* __restrict__ ent1,
                             const float* __restrict__ a_w, int n0, int ntot) {
    int node = (blockIdx.x * blockDim.x + threadIdx.x) >> 5;
    int lane = threadIdx.x & 31;
    if (node >= ntot) return;
    const float* row = (node < n0) ? ent0 + (size_t)node * DIM
                                   : ent1 + (size_t)(node - n0) * DIM;
    float s = 0.f;
    #pragma unroll
    for (int d = lane; d < DIM; d += 32) s += row[d] * a_w[d];
    for (int o = 16; o; o >>= 1) s += __shfl_xor_sync(0xffffffffu, s, o);
    if (lane == 0) g_entdot[node] = s;
}
__global__ void hist_tri_all_k(const int* __restrict__ t0, const int* __restrict__ t1,
                               int ne0, int netot, int n0) {
    int e = blockIdx.x * blockDim.x + threadIdx.x;
    if (e >= netot) return;
    int head = (e < ne0) ? t0[3 * e] : n0 + t1[3 * (e - ne0)];
    atomicAdd(&g_cnt[head], 1);
}
__global__ void scan_blk_k(int n) {
    __shared__ int wsum[32];
    int b = blockIdx.x;
    int i = b * 1024 + threadIdx.x;
    int lane = threadIdx.x & 31, wid = threadIdx.x >> 5;
    int v = (i < n) ? g_cnt[i] : 0;
    int x = v;
    #pragma unroll
    for (int o = 1; o < 32; o <<= 1) {
        int y = __shfl_up_sync(0xffffffffu, x, o);
        if (lane >= o) x += y;
    }
    if (lane == 31) wsum[wid] = x;
    __syncthreads();
    if (wid == 0) {
        int w = wsum[lane];
        int xs = w;
        #pragma unroll
        for (int o = 1; o < 32; o <<= 1) {
            int y = __shfl_up_sync(0xffffffffu, xs, o);
            if (lane >= o) xs += y;
        }
        wsum[lane] = xs - w;
    }
    __syncthreads();
    int excl = wsum[wid] + x - v;
    if (i < n) g_ptr[i] = excl;
    if (threadIdx.x == 1023) g_bsum[b] = excl + v;
}
__global__ void scan_mid_k(int nb, int n) {
    int lane = threadIdx.x;
    int carry = 0;
    for (int base = 0; base < nb; base += 32) {
        int i = base + lane;
        int v = (i < nb) ? g_bsum[i] : 0;
        int x = v;
        #pragma unroll
        for (int o = 1; o < 32; o <<= 1) {
            int y = __shfl_up_sync(0xffffffffu, x, o);
            if (lane >= o) x += y;
        }
        if (i < nb) g_boff[i] = carry + x - v;
        carry += __shfl_sync(0xffffffffu, x, 31);
    }
    if (lane == 0) g_ptr[n] = carry;
}
__global__ void scan_add_k(int n) {
    int i = blockIdx.x * blockDim.x + threadIdx.x;
    if (i < n) {
        int p = g_ptr[i] + g_boff[i >> 10];
        g_ptr[i] = p;
        g_fill[i] = p;
    }
}
__global__ void scatter_tri_all_k(const int* __restrict__ t0, const int* __restrict__ t1,
                                  int ne0, int netot, int n0) {
    int e = blockIdx.x * blockDim.x + threadIdx.x;
    if (e >= netot) return;
    int head = (e < ne0) ? t0[3 * e] : n0 + t1[3 * (e - ne0)];
    int pos = atomicAdd(&g_fill[head], 1);
    g_idx[pos] = e;
}
__global__ void edge_ptr_all_k(const int* __restrict__ r0, const int* __restrict__ r1,
                               int E0, int Etot, int n0, int ntot) {
    int e = blockIdx.x * blockDim.x + threadIdx.x;
    if (e >= Etot) return;
    int r = (e < E0) ? r0[e] : n0 + r1[e - E0];
    if (e == 0) {
        for (int v = 0; v <= r; v++) g_eptr[v] = 0;
    } else {
        int rp = (e - 1 < E0) ? r0[e - 1] : n0 + r1[e - 1 - E0];
        for (int v = rp + 1; v <= r; v++) g_eptr[v] = e;
    }
    if (e == Etot - 1) {
        for (int v = r + 1; v <= ntot; v++) g_eptr[v] = Etot;
    }
}
__global__ void attr_agg_all_k(const int* __restrict__ t0, const int* __restrict__ t1,
                               int ne0,
                               const float* __restrict__ ab_ptr,
                               const float* __restrict__ ent0, const float* __restrict__ ent1,
                               int n0) {
    int v = blockIdx.x;
    int t = threadIdx.x;
    int s = g_ptr[v], e = g_ptr[v + 1];
    int side = v >= n0;
    const int* tri = side ? t1 : t0;
    int tbase = side ? ne0 : 0;
    __shared__ float sred[2];
    __shared__ float s_inv;
    __shared__ float sh_p[64];
    __shared__ int sh_att[64];
    __shared__ int sh_val[64];
    float ab = ab_ptr[0];
    float ed = g_entdot[v];
    float part = 0.f;
    for (int i = s + t; i < e; i += 64) {
        int tt = g_idx[i] - tbase;
        float sc = ed + g_attdot[tri[3 * tt + 2]] + ab;
        sc = sc > 0.f ? sc : 0.2f * sc;
        part += expf(sc);
    }
    for (int o = 16; o; o >>= 1) part += __shfl_xor_sync(0xffffffffu, part, o);
    if ((t & 31) == 0) sred[t >> 5] = part;
    __syncthreads();
    if (t == 0) {
        float rs = sred[0] + sred[1];
        s_inv = (rs > 0.f) ? 1.f / rs : 0.f;
    }
    __syncthreads();
    float inv_rs = s_inv;
    float4 acc = make_float4(0.f, 0.f, 0.f, 0.f);
    for (int base = s; base < e; base += 64) {
        int cnt = min(64, e - base);
        if (t < cnt) {
            int tt = g_idx[base + t] - tbase;
            int att = tri[3 * tt + 2];
            int val = tri[3 * tt + 1];
            sh_att[t] = att;
            sh_val[t] = val;
            float sc = ed + g_attdot[att] + ab;
            sc = sc > 0.f ? sc : 0.2f * sc;
            sh_p[t] = expf(sc) * inv_rs;
        }
        __syncthreads();
        for (int j = 0; j < cnt; j++) {
            float p = sh_p[j];
            const float4 aw = *(const float4*)&g_attW[(size_t)sh_att[j] * DIM + t * 4];
            const float4 vw = *(const float4*)&g_valW[(size_t)sh_val[j] * DIM + t * 4];
            acc.x += p * (aw.x + vw.x);
            acc.y += p * (aw.y + vw.y);
            acc.z += p * (aw.z + vw.z);
            acc.w += p * (aw.w + vw.w);
        }
        __syncthreads();
    }
    const float* ef_row = side ? ent1 + (size_t)(v - n0) * DIM : ent0 + (size_t)v * DIM;
    const float4 ef = *(const float4*)&ef_row[t * 4];
    float4 x = make_float4(acc.x + ef.x, acc.y + ef.y, acc.z + ef.z, acc.w + ef.w);
    x.x = x.x > 0.f ? x.x : expm1f(x.x);
    x.y = x.y > 0.f ? x.y : expm1f(x.y);
    x.z = x.z > 0.f ? x.z : expm1f(x.z);
    x.w = x.w > 0.f ? x.w : expm1f(x.w);
    *(float4*)&g_F1[(size_t)v * DIM + t * 4] = x;
}
__global__ void gcn_agg_split_all_k(const float* __restrict__ feats,
                                    const int* __restrict__ c0, const int* __restrict__ c1,
                                    int E0, int n0,
                                    __nv_bfloat16* __restrict__ hi,
                                    __nv_bfloat16* __restrict__ lo) {
    int v = blockIdx.x;
    int t = threadIdx.x;
    int s = g_eptr[v], e = g_eptr[v + 1];
    __shared__ int sh_c[64];
    float4 acc = make_float4(0.f, 0.f, 0.f, 0.f);
    for (int base = s; base < e; base += 64) {
        int cnt = min(64, e - base);
        if (t < cnt) {
            int i = base + t;
            sh_c[t] = (i < E0) ? c0[i] : n0 + c1[i - E0];
        }
        __syncthreads();
        for (int j = 0; j < cnt; j++) {
            const float4 f = *(const float4*)&feats[(size_t)sh_c[j] * DIM + t * 4];
            acc.x += f.x; acc.y += f.y; acc.z += f.z; acc.w += f.w;
        }
        __syncthreads();
    }
    float inv = (e > s) ? 1.f / (float)(e - s) : 0.f;
    float vals[4] = {acc.x * inv, acc.y * inv, acc.z * inv, acc.w * inv};
    __nv_bfloat16 hv[4], lv[4];
    #pragma unroll
    for (int j = 0; j < 4; j++) {
        hv[j] = __float2bfloat16(vals[j]);
        lv[j] = __float2bfloat16(vals[j] - __bfloat162float(hv[j]));
    }
    *(uint2*)&hi[(size_t)v * DIM + t * 4] = *(uint2*)hv;
    *(uint2*)&lo[(size_t)v * DIM + t * 4] = *(uint2*)lv;
}
__global__ void l2norm_all_k(const float* __restrict__ in, float* __restrict__ out) {
    int v = blockIdx.x;
    int t = threadIdx.x;
    __shared__ float sred[2];
    __shared__ float s_inv;
    const float4 x = *(const float4*)&in[(size_t)v * DIM + t * 4];
    float sq = x.x * x.x + x.y * x.y + x.z * x.z + x.w * x.w;
    for (int o = 16; o; o >>= 1) sq += __shfl_xor_sync(0xffffffffu, sq, o);
    if ((t & 31) == 0) sred[t >> 5] = sq;
    __syncthreads();
    if (t == 0) {
        float nrm = sqrtf(sred[0] + sred[1]);
        s_inv = 1.f / fmaxf(nrm, 1e-12f);
    }
    __syncthreads();
    float inv = s_inv;
    float4 y = make_float4(x.x * inv, x.y * inv, x.z * inv, x.w * inv);
    *(float4*)&out[(size_t)v * DIM + t * 4] = y;
}
__global__ void gather_all_k(const int* __restrict__ s0, const int* __restrict__ s1,
                             int nseed, int n0,
                             const float* __restrict__ src, float* __restrict__ dst) {
    int i = blockIdx.x;
    int t = threadIdx.x;
    int node = (i < nseed) ? s0[i] : n0 + s1[i - nseed];
    *(float4*)&dst[(size_t)i * DIM + t * 4] =
        *(const float4*)&src[(size_t)node * DIM + t * 4];
}

// ---------------- host orchestration ----------------
static inline int ceildiv(int a, int b) { return (a + b - 1) / b; }

extern "C" void kernel_launch(void* const* d_in, const int* in_sizes, int n_in,
                              void* d_out, int out_size) {
    const int* seed_sr = (const int*)d_in[0];
    const int* seed_tg = (const int*)d_in[1];
    const int* tri_sr  = (const int*)d_in[2];
    const int* tri_tg  = (const int*)d_in[3];
    const int* rows_sr = (const int*)d_in[4];
    const int* cols_sr = (const int*)d_in[5];
    const int* rows_tg = (const int*)d_in[6];
    const int* cols_tg = (const int*)d_in[7];
    const float* att_feats = (const float*)d_in[8];
    const float* val_feats = (const float*)d_in[9];
    const float* ent_sr = (const float*)d_in[10];
    const float* ent_tg = (const float*)d_in[11];
    const float* a_w   = (const float*)d_in[12];
    const float* a_b   = (const float*)d_in[13];
    const float* W_enc = (const float*)d_in[14];
    const float* w1    = (const float*)d_in[15];
    const float* b1    = (const float*)d_in[16];
    const float* w2    = (const float*)d_in[17];
    const float* b2    = (const float*)d_in[18];
    (void)n_in; (void)out_size;

    const int nseed  = in_sizes[0];
    const int ne0    = in_sizes[2] / 3;
    const int ne1    = in_sizes[3] / 3;
    const int E0     = in_sizes[4];
    const int E1     = in_sizes[6];
    const int natt   = in_sizes[8] / DIM;
    const int nval   = in_sizes[9] / 300;
    const int n0     = in_sizes[10] / DIM;
    const int n1     = in_sizes[11] / DIM;
    const int ntot   = n0 + n1;
    const int netot  = ne0 + ne1;
    const int Etot   = E0 + E1;

    static cudaStream_t s_aux = nullptr;
    static cudaEvent_t ev_fork = nullptr, ev_join = nullptr;
    if (!s_aux) {
        cudaStreamCreateWithFlags(&s_aux, cudaStreamNonBlocking);
        cudaEventCreateWithFlags(&ev_fork, cudaEventDisableTiming);
        cudaEventCreateWithFlags(&ev_join, cudaEventDisableTiming);
        cudaFuncSetAttribute(mma_gemm_k<0>, cudaFuncAttributeMaxDynamicSharedMemorySize, SMEM_TOT);
        cudaFuncSetAttribute(mma_gemm_k<1>, cudaFuncAttributeMaxDynamicSharedMemorySize, SMEM_TOT);
        cudaFuncSetAttribute(mma_gemm_k<2>, cudaFuncAttributeMaxDynamicSharedMemorySize, SMEM_TOT);
    }

    float* valW;  cudaGetSymbolAddress((void**)&valW,  g_valW);
    float* F1;    cudaGetSymbolAddress((void**)&F1,    g_F1);
    float* F2;    cudaGetSymbolAddress((void**)&F2,    g_F2);
    int*   cntp;  cudaGetSymbolAddress((void**)&cntp,  g_cnt);
    __nv_bfloat16 *xaH, *xaL, *wetH, *wetL, *w1tH, *w1tL, *w2tH, *w2tL;
    cudaGetSymbolAddress((void**)&xaH, g_xa_h);
    cudaGetSymbolAddress((void**)&xaL, g_xa_l);
    cudaGetSymbolAddress((void**)&wetH, g_wet_h);
    cudaGetSymbolAddress((void**)&wetL, g_wet_l);
    cudaGetSymbolAddress((void**)&w1tH, g_w1t_h);
    cudaGetSymbolAddress((void**)&w1tL, g_w1t_l);
    cudaGetSymbolAddress((void**)&w2tH, g_w2t_h);
    cudaGetSymbolAddress((void**)&w2tL, g_w2t_l);

    float* out = (float*)d_out;
    float* out_seed = out;
    float* out_full = out + (size_t)2 * nseed * DIM;

    // ---- precompute; valW pipeline forked to aux stream ----
    tsplit_k<<<ceildiv(256 * KPAD_VAL, 256), 256>>>(
        W_enc + (size_t)DIM * DIM, 300, KPAD_VAL, wetH, wetL);
    cudaEventRecord(ev_fork, 0);
    cudaStreamWaitEvent(s_aux, ev_fork, 0);
    {
        long long tot = (long long)nval * KPAD_VAL;
        split_pad_k<<<(int)((tot + 255) / 256), 256, 0, s_aux>>>(
            val_feats, nval, 300, KPAD_VAL, xaH, xaL);
        dim3 grid(2, ceildiv(nval, 128));
        mma_gemm_k<0><<<grid, 128, SMEM_TOT, s_aux>>>(
            xaH, xaL, KPAD_VAL, wetH, wetL, nval, nullptr, nullptr, valW);
    }
    cudaEventRecord(ev_join, s_aux);
    att_k<<<natt, DIM>>>(att_feats, W_enc, a_w, natt);
    tsplit_k<<<ceildiv(256 * 256, 256), 256>>>(w1, 256, 256, w1tH, w1tL);
    tsplit_k<<<ceildiv(256 * 256, 256), 256>>>(w2, 256, 256, w2tH, w2tL);
    entdot_all_k<<<ceildiv(ntot * 32, 256), 256>>>(ent_sr, ent_tg, a_w, n0, ntot);
    zero_int_k<<<ceildiv(ntot, 256), 256>>>(cntp, ntot);
    hist_tri_all_k<<<ceildiv(netot, 256), 256>>>(tri_sr, tri_tg, ne0, netot, n0);
    int nb = ceildiv(ntot, 1024);
    scan_blk_k<<<nb, 1024>>>(ntot);
    scan_mid_k<<<1, 32>>>(nb, ntot);
    scan_add_k<<<ceildiv(ntot, 256), 256>>>(ntot);
    scatter_tri_all_k<<<ceildiv(netot, 256), 256>>>(tri_sr, tri_tg, ne0, netot, n0);
    edge_ptr_all_k<<<ceildiv(Etot, 256), 256>>>(rows_sr, rows_tg, E0, Etot, n0, ntot);

    // ---- join: attr encoder needs valW ----
    cudaStreamWaitEvent(0, ev_join, 0);
    attr_agg_all_k<<<ntot, 64>>>(tri_sr, tri_tg, ne0, a_b, ent_sr, ent_tg, n0);

    // ---- stacked GCN layers ----
    dim3 ggrid(2, ceildiv(ntot, 128));
    gcn_agg_split_all_k<<<ntot, 64>>>(F1, cols_sr, cols_tg, E0, n0, xaH, xaL);
    mma_gemm_k<1><<<ggrid, 128, SMEM_TOT>>>(xaH, xaL, 256, w1tH, w1tL, ntot, b1, F1, F2);
    gcn_agg_split_all_k<<<ntot, 64>>>(F2, cols_sr, cols_tg, E0, n0, xaH, xaL);
    mma_gemm_k<2><<<ggrid, 128, SMEM_TOT>>>(xaH, xaL, 256, w2tH, w2tL, ntot, b2, F2, F1);

    // ---- output ----
    l2norm_all_k<<<ntot, 64>>>(F1, out_full);
    gather_all_k<<<2 * nseed, 64>>>(seed_sr, seed_tg, nseed, n0, out_full, out_seed);
}

// round 11
// speedup vs baseline: 1.1721x; 1.1721x over previous
#include <cuda_runtime.h>
#include <cuda_bf16.h>
#include <math.h>
#include <stdint.h>

#define DIM 256
#define NTOT 100000
#define ETRI 400000
#define NVALMAX 100000
#define NATTMAX 1001
#define KPAD_VAL 320
#define MT_S 40   // smem row stride in bf16 (80B): conflict-free for ldmatrix 8-row phases

// dynamic smem per buffer: A 128xMT_S hi+lo, B 128xMT_S hi+lo
#define OFF_AH 0
#define OFF_AL 10240
#define OFF_BH 20480
#define OFF_BL 30720
#define BUFSZ  40960
#define SMEM_TOT (2 * BUFSZ)

// ---------------- scratch ----------------
__device__ float g_valW[NVALMAX * DIM];
__device__ float g_attW[NATTMAX * DIM];
__device__ float g_attdot[NATTMAX];
__device__ float g_entdot[NTOT];
__device__ int   g_cnt[NTOT];
__device__ int   g_ptr[NTOT + 1];
__device__ int   g_eptr[NTOT + 1];
__device__ int   g_fill[NTOT];
__device__ int   g_idx[ETRI];
__device__ int   g_bsum[128];
__device__ int   g_boff[128];
__device__ float g_F1[NTOT * DIM];
__device__ float g_F2[NTOT * DIM];
__device__ __nv_bfloat16 g_xa_h[NTOT * DIM];
__device__ __nv_bfloat16 g_xa_l[NTOT * DIM];
__device__ __nv_bfloat16 g_wet_h[DIM * KPAD_VAL];
__device__ __nv_bfloat16 g_wet_l[DIM * KPAD_VAL];
__device__ __nv_bfloat16 g_w1t_h[DIM * DIM];
__device__ __nv_bfloat16 g_w1t_l[DIM * DIM];
__device__ __nv_bfloat16 g_w2t_h[DIM * DIM];
__device__ __nv_bfloat16 g_w2t_l[DIM * DIM];

// ---------------- PTX wrappers ----------------
__device__ __forceinline__ void mma16816(float* c, const uint32_t* a, const uint32_t* b) {
    asm volatile(
        "mma.sync.aligned.m16n8k16.row.col.f32.bf16.bf16.f32 "
        "{%0,%1,%2,%3}, {%4,%5,%6,%7}, {%8,%9}, {%0,%1,%2,%3};"
        : "+f"(c[0]), "+f"(c[1]), "+f"(c[2]), "+f"(c[3])
        : "r"(a[0]), "r"(a[1]), "r"(a[2]), "r"(a[3]), "r"(b[0]), "r"(b[1]));
}
#define LDMX4(r0, r1, r2, r3, addr) \
    asm volatile("ldmatrix.sync.aligned.m8n8.x4.shared.b16 {%0,%1,%2,%3}, [%4];" \
        : "=r"(r0), "=r"(r1), "=r"(r2), "=r"(r3) : "r"(addr))
#define CP_ASYNC16(saddr, gptr) \
    asm volatile("cp.async.ca.shared.global [%0], [%1], 16;" :: "r"(saddr), "l"(gptr))
#define CP_COMMIT() asm volatile("cp.async.commit_group;" ::: "memory")
#define CP_WAIT1() asm volatile("cp.async.wait_group 1;" ::: "memory")
#define CP_WAIT0() asm volatile("cp.async.wait_group 0;" ::: "memory")

// ---------------- HMMA split GEMM: 128x128 CTA tile, 4 warps of 64x64 ----------------
// PRE=1: A pre-split bf16 hi/lo [M, Kpad], via cp.async.
// PRE=0: A fp32 [M, K], converted in-register to hi/lo and stored synchronously.
// B hi/lo [256, Kpad] via cp.async. D = AhBh + AlBh + AhBl (fp32 accum).
// MODE 0: C = AB ; MODE 1: C = res + relu(AB+bias) ; MODE 2: C = res + AB + bias
template <int MODE, int PRE>
__global__ void __launch_bounds__(128, 2)
mma_gemm_k(const void* __restrict__ Ap, const void* __restrict__ Ap2, int K, int Kpad,
           const __nv_bfloat16* __restrict__ Bh, const __nv_bfloat16* __restrict__ Bl,
           int M,
           const float* __restrict__ bias, const float* __restrict__ res,
           float* __restrict__ C) {
    extern __shared__ char smem_dyn[];
    uint32_t smem_b = (uint32_t)__cvta_generic_to_shared(smem_dyn);
    int tid = threadIdx.x;
    int wid = tid >> 5, lane = tid & 31;
    int wm = wid & 1;      // 2 warp-rows of 64
    int wn = wid >> 1;     // 2 warp-cols of 64
    int row0 = blockIdx.y * 128;
    int col0 = blockIdx.x * 128;

    float acc[4][8][4];
    #pragma unroll
    for (int mt = 0; mt < 4; mt++)
        #pragma unroll
        for (int nt = 0; nt < 8; nt++)
            #pragma unroll
            for (int q = 0; q < 4; q++) acc[mt][nt][q] = 0.f;

    // copy mapping: thread t handles A row t and B row t (128 rows each)
    int gr = row0 + tid;
    bool arow_ok = gr < M;
    const float* Arow = (const float*)Ap + (size_t)(arow_ok ? gr : 0) * K;
    const __nv_bfloat16* AhRow = (const __nv_bfloat16*)Ap + (size_t)(arow_ok ? gr : 0) * Kpad;
    const __nv_bfloat16* AlRow = (const __nv_bfloat16*)Ap2 + (size_t)(arow_ok ? gr : 0) * Kpad;
    const __nv_bfloat16* BhRow = Bh + (size_t)(col0 + tid) * Kpad;
    const __nv_bfloat16* BlRow = Bl + (size_t)(col0 + tid) * Kpad;
    uint32_t srow = (uint32_t)(tid * MT_S * 2);

    auto copyChunk = [&](int buf, int k0) {
        uint32_t b = smem_b + buf * BUFSZ + srow;
        if (PRE) {
            #pragma unroll
            for (int j = 0; j < 4; j++) {
                uint32_t so = (uint32_t)(j * 16);
                CP_ASYNC16(b + OFF_AH + so, AhRow + k0 + j * 8);
                CP_ASYNC16(b + OFF_AL + so, AlRow + k0 + j * 8);
            }
        } else {
            // synchronous fp32 load + in-register hi/lo split + STS
            float aF[32];
            #pragma unroll
            for (int j = 0; j < 8; j++) {
                int gk = k0 + j * 4;
                float4 v = make_float4(0.f, 0.f, 0.f, 0.f);
                if (arow_ok && gk + 3 < K) v = *(const float4*)(Arow + gk);
                else if (arow_ok) {
                    float tmp[4] = {0.f, 0.f, 0.f, 0.f};
                    #pragma unroll
                    for (int u = 0; u < 4; u++) if (gk + u < K) tmp[u] = Arow[gk + u];
                    v = make_float4(tmp[0], tmp[1], tmp[2], tmp[3]);
                }
                aF[j * 4 + 0] = v.x; aF[j * 4 + 1] = v.y;
                aF[j * 4 + 2] = v.z; aF[j * 4 + 3] = v.w;
            }
            __nv_bfloat16 h[32], l[32];
            #pragma unroll
            for (int j = 0; j < 32; j++) {
                h[j] = __float2bfloat16(aF[j]);
                l[j] = __float2bfloat16(aF[j] - __bfloat162float(h[j]));
            }
            char* base = smem_dyn + buf * BUFSZ + tid * MT_S * 2;
            #pragma unroll
            for (int j = 0; j < 4; j++) {
                *(uint4*)(base + OFF_AH + j * 16) = ((const uint4*)h)[j];
                *(uint4*)(base + OFF_AL + j * 16) = ((const uint4*)l)[j];
            }
        }
        #pragma unroll
        for (int j = 0; j < 4; j++) {
            uint32_t so = (uint32_t)(j * 16);
            CP_ASYNC16(b + OFF_BH + so, BhRow + k0 + j * 8);
            CP_ASYNC16(b + OFF_BL + so, BlRow + k0 + j * 8);
        }
        CP_COMMIT();
    };

    // ldmatrix lane-address components
    int a_row = wm * 64 + (lane & 15);                         // + mt*16
    int a_colsel = (lane >> 4) * 8;
    int b_row = wn * 64 + ((lane >> 4) ? 8 : 0) + (lane & 7);  // + p*16
    int b_colsel = ((lane >> 3) & 1) * 8;

    int nch = Kpad / 32;
    copyChunk(0, 0);
    if (nch > 1) copyChunk(1, 32);

    for (int ci = 0; ci < nch; ci++) {
        if (ci + 1 < nch) { CP_WAIT1(); } else { CP_WAIT0(); }
        __syncthreads();
        uint32_t bufb = smem_b + (ci & 1) * BUFSZ;
        #pragma unroll
        for (int ks = 0; ks < 2; ks++) {
            uint32_t aH[4][4], aL[4][4];
            #pragma unroll
            for (int mt = 0; mt < 4; mt++) {
                uint32_t off = (uint32_t)(((a_row + mt * 16) * MT_S + ks * 16 + a_colsel) * 2);
                LDMX4(aH[mt][0], aH[mt][1], aH[mt][2], aH[mt][3], bufb + OFF_AH + off);
                LDMX4(aL[mt][0], aL[mt][1], aL[mt][2], aL[mt][3], bufb + OFF_AL + off);
            }
            #pragma unroll
            for (int p = 0; p < 4; p++) {
                uint32_t off = (uint32_t)(((b_row + p * 16) * MT_S + ks * 16 + b_colsel) * 2);
                uint32_t h0, h1, h2, h3, l0, l1, l2, l3;
                LDMX4(h0, h1, h2, h3, bufb + OFF_BH + off);
                LDMX4(l0, l1, l2, l3, bufb + OFF_BL + off);
                uint32_t bH0[2] = {h0, h1}, bH1[2] = {h2, h3};
                uint32_t bL0[2] = {l0, l1}, bL1[2] = {l2, l3};
                #pragma unroll
                for (int mt = 0; mt < 4; mt++) {
                    mma16816(acc[mt][2 * p],     aH[mt], bH0);
                    mma16816(acc[mt][2 * p],     aL[mt], bH0);
                    mma16816(acc[mt][2 * p],     aH[mt], bL0);
                    mma16816(acc[mt][2 * p + 1], aH[mt], bH1);
                    mma16816(acc[mt][2 * p + 1], aL[mt], bH1);
                    mma16816(acc[mt][2 * p + 1], aH[mt], bL1);
                }
            }
        }
        __syncthreads();   // all warps done reading buf(ci) before it is refilled
        if (ci + 2 < nch) copyChunk(ci & 1, (ci + 2) * 32);
    }

    #pragma unroll
    for (int mt = 0; mt < 4; mt++) {
        #pragma unroll
        for (int half = 0; half < 2; half++) {
            int r = row0 + wm * 64 + mt * 16 + (lane >> 2) + half * 8;
            if (r >= M) continue;
            #pragma unroll
            for (int nt = 0; nt < 8; nt++) {
                int c = col0 + wn * 64 + nt * 8 + (lane & 3) * 2;
                float2 v;
                v.x = acc[mt][nt][half * 2 + 0];
                v.y = acc[mt][nt][half * 2 + 1];
                if (MODE >= 1) {
                    const float2 bb = *(const float2*)&bias[c];
                    v.x += bb.x; v.y += bb.y;
                    if (MODE == 1) { v.x = fmaxf(v.x, 0.f); v.y = fmaxf(v.y, 0.f); }
                    const float2 rr = *(const float2*)&res[(size_t)r * 256 + c];
                    v.x += rr.x; v.y += rr.y;
                }
                *(float2*)&C[(size_t)r * 256 + c] = v;
            }
        }
    }
}

// ---------------- weight transpose + hi/lo split ----------------
__global__ void tsplit_k(const float* __restrict__ src, int K, int Kpad,
                         __nv_bfloat16* __restrict__ hi, __nv_bfloat16* __restrict__ lo) {
    int idx = blockIdx.x * blockDim.x + threadIdx.x;
    if (idx >= 256 * Kpad) return;
    int k = idx % Kpad;
    int n = idx / Kpad;
    float v = (k < K) ? src[(size_t)k * 256 + n] : 0.f;
    __nv_bfloat16 h = __float2bfloat16(v);
    hi[idx] = h;
    lo[idx] = __float2bfloat16(v - __bfloat162float(h));
}

// ---------------- stacked SIMT pipeline kernels ----------------
__global__ void zero_int_k(int* p, int n) {
    int i = blockIdx.x * blockDim.x + threadIdx.x;
    if (i < n) p[i] = 0;
}
__global__ void att_k(const float* __restrict__ att_feats,
                      const float* __restrict__ W_enc,
                      const float* __restrict__ a_w, int natt) {
    int r = blockIdx.x;
    int d = threadIdx.x;
    __shared__ float sh[DIM];
    __shared__ float sred[8];
    sh[d] = att_feats[(size_t)r * DIM + d];
    __syncthreads();
    float acc = 0.f;
    #pragma unroll 8
    for (int k = 0; k < DIM; k++) acc += sh[k] * W_enc[(size_t)k * DIM + d];
    g_attW[(size_t)r * DIM + d] = acc;
    float v = sh[d] * a_w[DIM + d];
    for (int o = 16; o; o >>= 1) v += __shfl_xor_sync(0xffffffffu, v, o);
    if ((d & 31) == 0) sred[d >> 5] = v;
    __syncthreads();
    if (d == 0) {
        float s = 0.f;
        #pragma unroll
        for (int i = 0; i < 8; i++) s += sred[i];
        g_attdot[r] = s;
    }
}
__global__ void entdot_all_k(const float* __restrict__ ent0, const float* __restrict__ ent1,
                             const float* __restrict__ a_w, int n0, int ntot) {
    int node = (blockIdx.x * blockDim.x + threadIdx.x) >> 5;
    int lane = threadIdx.x & 31;
    if (node >= ntot) return;
    const float* row = (node < n0) ? ent0 + (size_t)node * DIM
                                   : ent1 + (size_t)(node - n0) * DIM;
    float s = 0.f;
    #pragma unroll
    for (int d = lane; d < DIM; d += 32) s += row[d] * a_w[d];
    for (int o = 16; o; o >>= 1) s += __shfl_xor_sync(0xffffffffu, s, o);
    if (lane == 0) g_entdot[node] = s;
}
__global__ void hist_tri_all_k(const int* __restrict__ t0, const int* __restrict__ t1,
                               int ne0, int netot, int n0) {
    int e = blockIdx.x * blockDim.x + threadIdx.x;
    if (e >= netot) return;
    int head = (e < ne0) ? t0[3 * e] : n0 + t1[3 * (e - ne0)];
    atomicAdd(&g_cnt[head], 1);
}
__global__ void scan_blk_k(int n) {
    __shared__ int wsum[32];
    int b = blockIdx.x;
    int i = b * 1024 + threadIdx.x;
    int lane = threadIdx.x & 31, wid = threadIdx.x >> 5;
    int v = (i < n) ? g_cnt[i] : 0;
    int x = v;
    #pragma unroll
    for (int o = 1; o < 32; o <<= 1) {
        int y = __shfl_up_sync(0xffffffffu, x, o);
        if (lane >= o) x += y;
    }
    if (lane == 31) wsum[wid] = x;
    __syncthreads();
    if (wid == 0) {
        int w = wsum[lane];
        int xs = w;
        #pragma unroll
        for (int o = 1; o < 32; o <<= 1) {
            int y = __shfl_up_sync(0xffffffffu, xs, o);
            if (lane >= o) xs += y;
        }
        wsum[lane] = xs - w;
    }
    __syncthreads();
    int excl = wsum[wid] + x - v;
    if (i < n) g_ptr[i] = excl;
    if (threadIdx.x == 1023) g_bsum[b] = excl + v;
}
__global__ void scan_mid_k(int nb, int n) {
    int lane = threadIdx.x;
    int carry = 0;
    for (int base = 0; base < nb; base += 32) {
        int i = base + lane;
        int v = (i < nb) ? g_bsum[i] : 0;
        int x = v;
        #pragma unroll
        for (int o = 1; o < 32; o <<= 1) {
            int y = __shfl_up_sync(0xffffffffu, x, o);
            if (lane >= o) x += y;
        }
        if (i < nb) g_boff[i] = carry + x - v;
        carry += __shfl_sync(0xffffffffu, x, 31);
    }
    if (lane == 0) g_ptr[n] = carry;
}
__global__ void scan_add_k(int n) {
    int i = blockIdx.x * blockDim.x + threadIdx.x;
    if (i < n) {
        int p = g_ptr[i] + g_boff[i >> 10];
        g_ptr[i] = p;
        g_fill[i] = p;
    }
}
__global__ void scatter_tri_all_k(const int* __restrict__ t0, const int* __restrict__ t1,
                                  int ne0, int netot, int n0) {
    int e = blockIdx.x * blockDim.x + threadIdx.x;
    if (e >= netot) return;
    int head = (e < ne0) ? t0[3 * e] : n0 + t1[3 * (e - ne0)];
    int pos = atomicAdd(&g_fill[head], 1);
    g_idx[pos] = e;
}
__global__ void edge_ptr_all_k(const int* __restrict__ r0, const int* __restrict__ r1,
                               int E0, int Etot, int n0, int ntot) {
    int e = blockIdx.x * blockDim.x + threadIdx.x;
    if (e >= Etot) return;
    int r = (e < E0) ? r0[e] : n0 + r1[e - E0];
    if (e == 0) {
        for (int v = 0; v <= r; v++) g_eptr[v] = 0;
    } else {
        int rp = (e - 1 < E0) ? r0[e - 1] : n0 + r1[e - 1 - E0];
        for (int v = rp + 1; v <= r; v++) g_eptr[v] = e;
    }
    if (e == Etot - 1) {
        for (int v = r + 1; v <= ntot; v++) g_eptr[v] = Etot;
    }
}
__global__ void attr_agg_all_k(const int* __restrict__ t0, const int* __restrict__ t1,
                               int ne0,
                               const float* __restrict__ ab_ptr,
                               const float* __restrict__ ent0, const float* __restrict__ ent1,
                               int n0) {
    int v = blockIdx.x;
    int t = threadIdx.x;
    int s = g_ptr[v], e = g_ptr[v + 1];
    int side = v >= n0;
    const int* tri = side ? t1 : t0;
    int tbase = side ? ne0 : 0;
    __shared__ float sred[2];
    __shared__ float s_inv;
    __shared__ float sh_p[64];
    __shared__ int sh_att[64];
    __shared__ int sh_val[64];
    float ab = ab_ptr[0];
    float ed = g_entdot[v];
    float part = 0.f;
    for (int i = s + t; i < e; i += 64) {
        int tt = g_idx[i] - tbase;
        float sc = ed + g_attdot[tri[3 * tt + 2]] + ab;
        sc = sc > 0.f ? sc : 0.2f * sc;
        part += expf(sc);
    }
    for (int o = 16; o; o >>= 1) part += __shfl_xor_sync(0xffffffffu, part, o);
    if ((t & 31) == 0) sred[t >> 5] = part;
    __syncthreads();
    if (t == 0) {
        float rs = sred[0] + sred[1];
        s_inv = (rs > 0.f) ? 1.f / rs : 0.f;
    }
    __syncthreads();
    float inv_rs = s_inv;
    float4 acc = make_float4(0.f, 0.f, 0.f, 0.f);
    for (int base = s; base < e; base += 64) {
        int cnt = min(64, e - base);
        if (t < cnt) {
            int tt = g_idx[base + t] - tbase;
            int att = tri[3 * tt + 2];
            int val = tri[3 * tt + 1];
            sh_att[t] = att;
            sh_val[t] = val;
            float sc = ed + g_attdot[att] + ab;
            sc = sc > 0.f ? sc : 0.2f * sc;
            sh_p[t] = expf(sc) * inv_rs;
        }
        __syncthreads();
        for (int j = 0; j < cnt; j++) {
            float p = sh_p[j];
            const float4 aw = *(const float4*)&g_attW[(size_t)sh_att[j] * DIM + t * 4];
            const float4 vw = *(const float4*)&g_valW[(size_t)sh_val[j] * DIM + t * 4];
            acc.x += p * (aw.x + vw.x);
            acc.y += p * (aw.y + vw.y);
            acc.z += p * (aw.z + vw.z);
            acc.w += p * (aw.w + vw.w);
        }
        __syncthreads();
    }
    const float* ef_row = side ? ent1 + (size_t)(v - n0) * DIM : ent0 + (size_t)v * DIM;
    const float4 ef = *(const float4*)&ef_row[t * 4];
    float4 x = make_float4(acc.x + ef.x, acc.y + ef.y, acc.z + ef.z, acc.w + ef.w);
    x.x = x.x > 0.f ? x.x : expm1f(x.x);
    x.y = x.y > 0.f ? x.y : expm1f(x.y);
    x.z = x.z > 0.f ? x.z : expm1f(x.z);
    x.w = x.w > 0.f ? x.w : expm1f(x.w);
    *(float4*)&g_F1[(size_t)v * DIM + t * 4] = x;
}
__global__ void gcn_agg_split_all_k(const float* __restrict__ feats,
                                    const int* __restrict__ c0, const int* __restrict__ c1,
                                    int E0, int n0,
                                    __nv_bfloat16* __restrict__ hi,
                                    __nv_bfloat16* __restrict__ lo) {
    int v = blockIdx.x;
    int t = threadIdx.x;
    int s = g_eptr[v], e = g_eptr[v + 1];
    __shared__ int sh_c[64];
    float4 acc = make_float4(0.f, 0.f, 0.f, 0.f);
    for (int base = s; base < e; base += 64) {
        int cnt = min(64, e - base);
        if (t < cnt) {
            int i = base + t;
            sh_c[t] = (i < E0) ? c0[i] : n0 + c1[i - E0];
        }
        __syncthreads();
        for (int j = 0; j < cnt; j++) {
            const float4 f = *(const float4*)&feats[(size_t)sh_c[j] * DIM + t * 4];
            acc.x += f.x; acc.y += f.y; acc.z += f.z; acc.w += f.w;
        }
        __syncthreads();
    }
    float inv = (e > s) ? 1.f / (float)(e - s) : 0.f;
    float vals[4] = {acc.x * inv, acc.y * inv, acc.z * inv, acc.w * inv};
    __nv_bfloat16 hv[4], lv[4];
    #pragma unroll
    for (int j = 0; j < 4; j++) {
        hv[j] = __float2bfloat16(vals[j]);
        lv[j] = __float2bfloat16(vals[j] - __bfloat162float(hv[j]));
    }
    *(uint2*)&hi[(size_t)v * DIM + t * 4] = *(uint2*)hv;
    *(uint2*)&lo[(size_t)v * DIM + t * 4] = *(uint2*)lv;
}
__global__ void l2norm_all_k(const float* __restrict__ in, float* __restrict__ out) {
    int v = blockIdx.x;
    int t = threadIdx.x;
    __shared__ float sred[2];
    __shared__ float s_inv;
    const float4 x = *(const float4*)&in[(size_t)v * DIM + t * 4];
    float sq = x.x * x.x + x.y * x.y + x.z * x.z + x.w * x.w;
    for (int o = 16; o; o >>= 1) sq += __shfl_xor_sync(0xffffffffu, sq, o);
    if ((t & 31) == 0) sred[t >> 5] = sq;
    __syncthreads();
    if (t == 0) {
        float nrm = sqrtf(sred[0] + sred[1]);
        s_inv = 1.f / fmaxf(nrm, 1e-12f);
    }
    __syncthreads();
    float inv = s_inv;
    float4 y = make_float4(x.x * inv, x.y * inv, x.z * inv, x.w * inv);
    *(float4*)&out[(size_t)v * DIM + t * 4] = y;
}
__global__ void gather_all_k(const int* __restrict__ s0, const int* __restrict__ s1,
                             int nseed, int n0,
                             const float* __restrict__ src, float* __restrict__ dst) {
    int i = blockIdx.x;
    int t = threadIdx.x;
    int node = (i < nseed) ? s0[i] : n0 + s1[i - nseed];
    *(float4*)&dst[(size_t)i * DIM + t * 4] =
        *(const float4*)&src[(size_t)node * DIM + t * 4];
}

// ---------------- host orchestration ----------------
static inline int ceildiv(int a, int b) { return (a + b - 1) / b; }

extern "C" void kernel_launch(void* const* d_in, const int* in_sizes, int n_in,
                              void* d_out, int out_size) {
    const int* seed_sr = (const int*)d_in[0];
    const int* seed_tg = (const int*)d_in[1];
    const int* tri_sr  = (const int*)d_in[2];
    const int* tri_tg  = (const int*)d_in[3];
    const int* rows_sr = (const int*)d_in[4];
    const int* cols_sr = (const int*)d_in[5];
    const int* rows_tg = (const int*)d_in[6];
    const int* cols_tg = (const int*)d_in[7];
    const float* att_feats = (const float*)d_in[8];
    const float* val_feats = (const float*)d_in[9];
    const float* ent_sr = (const float*)d_in[10];
    const float* ent_tg = (const float*)d_in[11];
    const float* a_w   = (const float*)d_in[12];
    const float* a_b   = (const float*)d_in[13];
    const float* W_enc = (const float*)d_in[14];
    const float* w1    = (const float*)d_in[15];
    const float* b1    = (const float*)d_in[16];
    const float* w2    = (const float*)d_in[17];
    const float* b2    = (const float*)d_in[18];
    (void)n_in; (void)out_size;

    const int nseed  = in_sizes[0];
    const int ne0    = in_sizes[2] / 3;
    const int ne1    = in_sizes[3] / 3;
    const int E0     = in_sizes[4];
    const int E1     = in_sizes[6];
    const int natt   = in_sizes[8] / DIM;
    const int nval   = in_sizes[9] / 300;
    const int n0     = in_sizes[10] / DIM;
    const int n1     = in_sizes[11] / DIM;
    const int ntot   = n0 + n1;
    const int netot  = ne0 + ne1;
    const int Etot   = E0 + E1;

    static cudaStream_t s_aux = nullptr;
    static cudaEvent_t ev_fork = nullptr, ev_join = nullptr;
    if (!s_aux) {
        cudaStreamCreateWithFlags(&s_aux, cudaStreamNonBlocking);
        cudaEventCreateWithFlags(&ev_fork, cudaEventDisableTiming);
        cudaEventCreateWithFlags(&ev_join, cudaEventDisableTiming);
        cudaFuncSetAttribute(mma_gemm_k<0, 0>, cudaFuncAttributeMaxDynamicSharedMemorySize, SMEM_TOT);
        cudaFuncSetAttribute(mma_gemm_k<1, 1>, cudaFuncAttributeMaxDynamicSharedMemorySize, SMEM_TOT);
        cudaFuncSetAttribute(mma_gemm_k<2, 1>, cudaFuncAttributeMaxDynamicSharedMemorySize, SMEM_TOT);
    }

    float* valW;  cudaGetSymbolAddress((void**)&valW,  g_valW);
    float* F1;    cudaGetSymbolAddress((void**)&F1,    g_F1);
    float* F2;    cudaGetSymbolAddress((void**)&F2,    g_F2);
    int*   cntp;  cudaGetSymbolAddress((void**)&cntp,  g_cnt);
    __nv_bfloat16 *xaH, *xaL, *wetH, *wetL, *w1tH, *w1tL, *w2tH, *w2tL;
    cudaGetSymbolAddress((void**)&xaH, g_xa_h);
    cudaGetSymbolAddress((void**)&xaL, g_xa_l);
    cudaGetSymbolAddress((void**)&wetH, g_wet_h);
    cudaGetSymbolAddress((void**)&wetL, g_wet_l);
    cudaGetSymbolAddress((void**)&w1tH, g_w1t_h);
    cudaGetSymbolAddress((void**)&w1tL, g_w1t_l);
    cudaGetSymbolAddress((void**)&w2tH, g_w2t_h);
    cudaGetSymbolAddress((void**)&w2tL, g_w2t_l);

    float* out = (float*)d_out;
    float* out_seed = out;
    float* out_full = out + (size_t)2 * nseed * DIM;

    // ---- precompute; valW GEMM (in-kernel fp32->hi/lo convert) forked to aux stream ----
    tsplit_k<<<ceildiv(256 * KPAD_VAL, 256), 256>>>(
        W_enc + (size_t)DIM * DIM, 300, KPAD_VAL, wetH, wetL);
    cudaEventRecord(ev_fork, 0);
    cudaStreamWaitEvent(s_aux, ev_fork, 0);
    {
        dim3 grid(2, ceildiv(nval, 128));
        mma_gemm_k<0, 0><<<grid, 128, SMEM_TOT, s_aux>>>(
            val_feats, nullptr, 300, KPAD_VAL, wetH, wetL, nval, nullptr, nullptr, valW);
    }
    cudaEventRecord(ev_join, s_aux);
    att_k<<<natt, DIM>>>(att_feats, W_enc, a_w, natt);
    tsplit_k<<<ceildiv(256 * 256, 256), 256>>>(w1, 256, 256, w1tH, w1tL);
    tsplit_k<<<ceildiv(256 * 256, 256), 256>>>(w2, 256, 256, w2tH, w2tL);
    entdot_all_k<<<ceildiv(ntot * 32, 256), 256>>>(ent_sr, ent_tg, a_w, n0, ntot);
    zero_int_k<<<ceildiv(ntot, 256), 256>>>(cntp, ntot);
    hist_tri_all_k<<<ceildiv(netot, 256), 256>>>(tri_sr, tri_tg, ne0, netot, n0);
    int nb = ceildiv(ntot, 1024);
    scan_blk_k<<<nb, 1024>>>(ntot);
    scan_mid_k<<<1, 32>>>(nb, ntot);
    scan_add_k<<<ceildiv(ntot, 256), 256>>>(ntot);
    scatter_tri_all_k<<<ceildiv(netot, 256), 256>>>(tri_sr, tri_tg, ne0, netot, n0);
    edge_ptr_all_k<<<ceildiv(Etot, 256), 256>>>(rows_sr, rows_tg, E0, Etot, n0, ntot);

    // ---- join: attr encoder needs valW ----
    cudaStreamWaitEvent(0, ev_join, 0);
    attr_agg_all_k<<<ntot, 64>>>(tri_sr, tri_tg, ne0, a_b, ent_sr, ent_tg, n0);

    // ---- stacked GCN layers ----
    dim3 ggrid(2, ceildiv(ntot, 128));
    gcn_agg_split_all_k<<<ntot, 64>>>(F1, cols_sr, cols_tg, E0, n0, xaH, xaL);
    mma_gemm_k<1, 1><<<ggrid, 128, SMEM_TOT>>>(xaH, xaL, 256, 256, w1tH, w1tL, ntot, b1, F1, F2);
    gcn_agg_split_all_k<<<ntot, 64>>>(F2, cols_sr, cols_tg, E0, n0, xaH, xaL);
    mma_gemm_k<2, 1><<<ggrid, 128, SMEM_TOT>>>(xaH, xaL, 256, 256, w2tH, w2tL, ntot, b2, F2, F1);

    // ---- output ----
    l2norm_all_k<<<ntot, 64>>>(F1, out_full);
    gather_all_k<<<2 * nseed, 64>>>(seed_sr, seed_tg, nseed, n0, out_full, out_seed);
}